// round 1
// baseline (speedup 1.0000x reference)
#include <cuda_runtime.h>

// ---------------------------------------------------------------------------
// KGEGraphEncoder: 2-layer relation-aware GAT, output = h[graph_offsets].
// Strategy: exact backward-frontier pruning. Only nodes/edges that can reach
// the 64 output rows are computed. Segment softmax is per-dst, so restricting
// to edges whose dst is in the frontier is mathematically exact. The
// segment_max subtraction is an algebraic no-op and is skipped.
// ---------------------------------------------------------------------------

#define N_NODES 50000
#define N_EDGES 800000
#define N_RELS  500
#define HID     128
#define NH      8
#define ND      16
#define NB      64
#define SLOPE   0.2f

// -------- static device scratch (no allocations allowed) --------
__device__ float g_feat[(size_t)N_NODES * HID];   // current-layer projected feat
__device__ float g_h1[(size_t)N_NODES * HID];     // layer-1 output
__device__ float g_el[N_NODES * NH];
__device__ float g_er[N_NODES * NH];
__device__ float g_denomA[N_NODES * NH];          // layer-1 softmax denom
__device__ float g_denomB[NB * NH];               // layer-2 softmax denom (per batch row)
__device__ float g_ex[(size_t)N_EDGES * NH];      // exp scores, indexed by compacted edge pos
__device__ int   g_E1[N_EDGES];                   // layer-1 surviving edge indices
__device__ int   g_E2[N_EDGES];                   // layer-2 surviving edge indices
__device__ int   g_listN0[N_NODES];               // nodes needing layer-1 feat
__device__ int   g_listN1[N_NODES];               // nodes needing layer-2 feat (= layer-1 out)
__device__ unsigned char g_maskS2[N_NODES];
__device__ unsigned char g_maskN1[N_NODES];
__device__ unsigned char g_maskN0[N_NODES];
__device__ int   g_b_of_node[N_NODES];            // node -> batch row (valid only on S2)
__device__ int   g_cnt[4];                        // 0:|E2| 1:|E1| 2:|N0| 3:|N1|
__device__ float g_rproj[2 * N_RELS * HID];       // per-layer relation projections
__device__ float g_ee[2 * N_RELS * NH];           // per-layer relation attention scores

// -------- kernels --------

__global__ void k_init(float* dout) {
    int i = blockIdx.x * blockDim.x + threadIdx.x;
    if (i < N_NODES) { g_maskS2[i] = 0; g_maskN1[i] = 0; g_maskN0[i] = 0; }
    if (i < NB * HID) dout[i] = 0.0f;
    if (i < NB * NH)  g_denomB[i] = 0.0f;
    if (i < 4)        g_cnt[i] = 0;
}

__global__ void k_seed(const int* __restrict__ offs) {
    int t = threadIdx.x;
    if (t < NB) {
        int n = offs[t];
        g_maskS2[n] = 1;
        g_maskN1[n] = 1;          // output nodes also need layer-1 output (er[dst])
        g_b_of_node[n] = t;
    }
}

// layer-2 edge filter: dst in S2
__global__ void k_filter2(const int* __restrict__ src, const int* __restrict__ dst) {
    int i = blockIdx.x * blockDim.x + threadIdx.x;
    if (i >= N_EDGES) return;
    int d = dst[i];
    if (g_maskS2[d]) {
        int p = atomicAdd(&g_cnt[0], 1);
        g_E2[p] = i;
        g_maskN1[src[i]] = 1;
    }
}

// layer-1 edge filter: dst in N1
__global__ void k_filter1(const int* __restrict__ src, const int* __restrict__ dst) {
    int i = blockIdx.x * blockDim.x + threadIdx.x;
    if (i >= N_EDGES) return;
    int d = dst[i];
    if (g_maskN1[d]) {
        int p = atomicAdd(&g_cnt[1], 1);
        g_E1[p] = i;
        g_maskN0[src[i]] = 1;
    }
}

__global__ void k_compact() {
    int i = blockIdx.x * blockDim.x + threadIdx.x;
    if (i >= N_NODES) return;
    unsigned char m1 = g_maskN1[i];
    if (g_maskN0[i] | m1) g_listN0[atomicAdd(&g_cnt[2], 1)] = i;
    if (m1)               g_listN1[atomicAdd(&g_cnt[3], 1)] = i;
}

// zero layer-1 accumulators at N1 nodes only
__global__ void k_zero1() {
    int j = threadIdx.x;
    int cnt = g_cnt[3];
    for (int idx = blockIdx.x; idx < cnt; idx += gridDim.x) {
        int n = g_listN1[idx];
        g_h1[(size_t)n * HID + j] = 0.0f;
        if (j < NH) g_denomA[n * NH + j] = 0.0f;
    }
}

// relation projection + relation attention scores, both layers (500 rels each)
__global__ void k_rel(const float* __restrict__ rel_table,
                      const float* __restrict__ W_rel,
                      const float* __restrict__ attn_e) {
    __shared__ float s[HID];
    int b = blockIdx.x;            // b = l*N_RELS + r
    int l = b / N_RELS;
    int r = b % N_RELS;
    int j = threadIdx.x;
    s[j] = rel_table[r * HID + j];
    __syncthreads();
    const float* W = W_rel + (size_t)l * HID * HID;
    float acc = 0.0f;
#pragma unroll
    for (int k = 0; k < HID; k++) acc += s[k] * W[k * HID + j];
    g_rproj[(size_t)b * HID + j] = acc;
    float v = acc * attn_e[l * HID + j];
    v += __shfl_xor_sync(0xffffffffu, v, 8);
    v += __shfl_xor_sync(0xffffffffu, v, 4);
    v += __shfl_xor_sync(0xffffffffu, v, 2);
    v += __shfl_xor_sync(0xffffffffu, v, 1);
    if ((j & 15) == 0) g_ee[b * NH + (j >> 4)] = v;
}

// node projection + el/er scores for one layer over the relevant node list
__global__ void k_node(int layer,
                       const float* __restrict__ ent_table,
                       const int*   __restrict__ ent_ids,
                       const float* __restrict__ W_ent,
                       const float* __restrict__ attn_l,
                       const float* __restrict__ attn_r) {
    __shared__ float s[HID];
    int j = threadIdx.x;
    int cnt = (layer == 0) ? g_cnt[2] : g_cnt[3];
    const int* list = (layer == 0) ? g_listN0 : g_listN1;
    const float* W = W_ent + (size_t)layer * HID * HID;
    float al = attn_l[layer * HID + j];
    float ar = attn_r[layer * HID + j];
    for (int idx = blockIdx.x; idx < cnt; idx += gridDim.x) {
        int n = list[idx];
        const float* row = (layer == 0)
            ? (ent_table + (size_t)ent_ids[n] * HID)
            : (g_h1 + (size_t)n * HID);
        __syncthreads();
        s[j] = row[j];
        __syncthreads();
        float acc = 0.0f;
#pragma unroll
        for (int k = 0; k < HID; k++) acc += s[k] * W[k * HID + j];
        g_feat[(size_t)n * HID + j] = acc;
        float v = acc * al;
        v += __shfl_xor_sync(0xffffffffu, v, 8);
        v += __shfl_xor_sync(0xffffffffu, v, 4);
        v += __shfl_xor_sync(0xffffffffu, v, 2);
        v += __shfl_xor_sync(0xffffffffu, v, 1);
        if ((j & 15) == 0) g_el[n * NH + (j >> 4)] = v;
        float w = acc * ar;
        w += __shfl_xor_sync(0xffffffffu, w, 8);
        w += __shfl_xor_sync(0xffffffffu, w, 4);
        w += __shfl_xor_sync(0xffffffffu, w, 2);
        w += __shfl_xor_sync(0xffffffffu, w, 1);
        if ((j & 15) == 0) g_er[n * NH + (j >> 4)] = w;
    }
}

// edge scores: ex = exp(leakyrelu(el[src]+er[dst]+ee[rel])), accumulate denom
__global__ void k_score(int layer,
                        const int* __restrict__ src,
                        const int* __restrict__ dst,
                        const int* __restrict__ rel_ids) {
    int cnt = (layer == 0) ? g_cnt[1] : g_cnt[0];
    const int* El = (layer == 0) ? g_E1 : g_E2;
    int t = blockIdx.x * blockDim.x + threadIdx.x;
    int h = t & 7;
    int e0 = t >> 3;
    int stride = (gridDim.x * blockDim.x) >> 3;
    for (int e = e0; e < cnt; e += stride) {
        int ei = El[e];
        int s = src[ei], d = dst[ei], r = rel_ids[ei];
        float v = g_el[s * NH + h] + g_er[d * NH + h]
                + g_ee[(layer * N_RELS + r) * NH + h];
        v = (v > 0.0f) ? v : SLOPE * v;
        float ex = expf(v);
        g_ex[(size_t)e * NH + h] = ex;
        if (layer == 0) atomicAdd(&g_denomA[d * NH + h], ex);
        else            atomicAdd(&g_denomB[g_b_of_node[d] * NH + h], ex);
    }
}

// aggregation: out[dst] += (feat[src] + rproj[rel]) * alpha
__global__ void k_agg(int layer,
                      const int* __restrict__ src,
                      const int* __restrict__ dst,
                      const int* __restrict__ rel_ids,
                      float* __restrict__ dout) {
    int cnt = (layer == 0) ? g_cnt[1] : g_cnt[0];
    const int* El = (layer == 0) ? g_E1 : g_E2;
    int t = blockIdx.x * blockDim.x + threadIdx.x;
    int j = t & 31;
    int e0 = t >> 5;
    int stride = (gridDim.x * blockDim.x) >> 5;
    for (int e = e0; e < cnt; e += stride) {
        int ei = El[e];
        int s = src[ei], d = dst[ei], r = rel_ids[ei];
        int h = j >> 2;
        float den = (layer == 0) ? g_denomA[d * NH + h]
                                 : g_denomB[g_b_of_node[d] * NH + h];
        float alpha = g_ex[(size_t)e * NH + h] / den;
        float4 f  = *(const float4*)(g_feat  + (size_t)s * HID + 4 * j);
        float4 rp = *(const float4*)(g_rproj + (size_t)(layer * N_RELS + r) * HID + 4 * j);
        float* ob = (layer == 0) ? (g_h1 + (size_t)d * HID)
                                 : (dout + (size_t)g_b_of_node[d] * HID);
        atomicAdd(ob + 4 * j + 0, (f.x + rp.x) * alpha);
        atomicAdd(ob + 4 * j + 1, (f.y + rp.y) * alpha);
        atomicAdd(ob + 4 * j + 2, (f.z + rp.z) * alpha);
        atomicAdd(ob + 4 * j + 3, (f.w + rp.w) * alpha);
    }
}

// -------- launch --------
extern "C" void kernel_launch(void* const* d_in, const int* in_sizes, int n_in,
                              void* d_out, int out_size) {
    const float* ent_table = (const float*)d_in[0];
    const float* rel_table = (const float*)d_in[1];
    const float* W_ent     = (const float*)d_in[2];
    const float* W_rel     = (const float*)d_in[3];
    const float* attn_l    = (const float*)d_in[4];
    const float* attn_r    = (const float*)d_in[5];
    const float* attn_e    = (const float*)d_in[6];
    const int*   ent_ids   = (const int*)d_in[7];
    const int*   rel_ids   = (const int*)d_in[8];
    const int*   src       = (const int*)d_in[9];
    const int*   dst       = (const int*)d_in[10];
    const int*   goffs     = (const int*)d_in[11];
    float*       out       = (float*)d_out;

    k_init<<<(N_NODES + 255) / 256, 256>>>(out);
    k_seed<<<1, 64>>>(goffs);
    k_filter2<<<(N_EDGES + 255) / 256, 256>>>(src, dst);
    k_filter1<<<(N_EDGES + 255) / 256, 256>>>(src, dst);
    k_compact<<<(N_NODES + 255) / 256, 256>>>();
    k_rel<<<2 * N_RELS, 128>>>(rel_table, W_rel, attn_e);
    k_zero1<<<1024, 128>>>();

    // layer 0 (full frontier N0)
    k_node<<<2048, 128>>>(0, ent_table, ent_ids, W_ent, attn_l, attn_r);
    k_score<<<512, 256>>>(0, src, dst, rel_ids);
    k_agg<<<512, 256>>>(0, src, dst, rel_ids, out);

    // layer 1 (frontier N1, output rows only)
    k_node<<<2048, 128>>>(1, ent_table, ent_ids, W_ent, attn_l, attn_r);
    k_score<<<64, 256>>>(1, src, dst, rel_ids);
    k_agg<<<64, 256>>>(1, src, dst, rel_ids, out);
}